// round 5
// baseline (speedup 1.0000x reference)
#include <cuda_runtime.h>

typedef unsigned long long ULL;

#define NBLK   128
#define NTHR   256
#define ROWS   32      // batch rows per block
#define T128   128
#define STEPS  60
#define HPU    34      // padded ULL stride per k-row of duplicated h (even -> 16B aligned)

__device__ __forceinline__ ULL fma2(ULL a, ULL b, ULL c) {
    ULL d;
    asm("fma.rn.f32x2 %0, %1, %2, %3;" : "=l"(d) : "l"(a), "l"(b), "l"(c));
    return d;
}
__device__ __forceinline__ ULL pack2(float x, float y) {
    ULL r;
    asm("mov.b64 %0, {%1, %2};" : "=l"(r) : "f"(x), "f"(y));
    return r;
}
__device__ __forceinline__ void unpack2(ULL v, float& x, float& y) {
    asm("mov.b64 {%0, %1}, %2;" : "=f"(x), "=f"(y) : "l"(v));
}
__device__ __forceinline__ float ex2f_(float x) {
    float y; asm("ex2.approx.f32 %0, %1;" : "=f"(y) : "f"(x)); return y;
}
__device__ __forceinline__ float rcpf_(float x) {
    float y; asm("rcp.approx.f32 %0, %1;" : "=f"(y) : "f"(x)); return y;
}
__device__ __forceinline__ float sigm(float x) {
    return rcpf_(1.0f + ex2f_(-1.4426950408889634f * x));
}
__device__ __forceinline__ float tanh_(float x) {
    return fmaf(2.0f, rcpf_(1.0f + ex2f_(-2.8853900817779268f * x)), -1.0f);
}

// 8 k-iterations of the matvec: acc_{if,go}[r] += W[k][j][{i,f},{g,o}] * hdup[k][R0+r]
__device__ __forceinline__ void mv8(const float* __restrict__ Wb,
                                    const ULL* __restrict__ hd,
                                    int j, int R0, int kb,
                                    ULL aif[8], ULL ago[8]) {
#pragma unroll
    for (int kk = 0; kk < 8; kk++) {
        int k = kb * 8 + kk;
        ulonglong2 w = *(const ulonglong2*)(Wb + ((k * 64 + j) << 2)); // w.x=(i,f) w.y=(g,o)
        const ULL* hr = hd + k * HPU + R0;
#pragma unroll
        for (int p = 0; p < 4; p++) {
            ulonglong2 hp = *(const ulonglong2*)(hr + 2 * p);  // rows 2p, 2p+1 (dup)
            aif[2 * p]     = fma2(w.x, hp.x, aif[2 * p]);
            aif[2 * p + 1] = fma2(w.x, hp.y, aif[2 * p + 1]);
            ago[2 * p]     = fma2(w.y, hp.x, ago[2 * p]);
            ago[2 * p + 1] = fma2(w.y, hp.y, ago[2 * p + 1]);
        }
    }
}

// one row of LSTM pointwise: gates (i,f) in aif, (g,o) in ago -> new c; returns new h
__device__ __forceinline__ float cell_row(ULL aif, ULL ago, float& c) {
    float gi, gf, gg, go;
    unpack2(aif, gi, gf);
    unpack2(ago, gg, go);
    float cn = sigm(gf) * c + sigm(gi) * tanh_(gg);
    c = cn;
    return sigm(go) * tanh_(cn);
}

// SMEM layout (floats):
//  W0    [64][64][4]   : Whh0 repacked, W0[(k*64+j)*4+gb] = Whh0[gb*64+j][k]
//  W1    [128][64][4]  : k<64 -> Wih1, k>=64 -> Whh1 (same repack)
//  hdup0 [64][HPU] ULL : duplicated h0 state, (h,h) per (k,row)
//  hdup1 [64][HPU] ULL
//  xs    [32][4]       : current step input per row
#define OFF_W0   0
#define OFF_W1   (OFF_W0 + 64 * 64 * 4)
#define OFF_H0D  (OFF_W1 + 128 * 64 * 4)
#define OFF_H1D  (OFF_H0D + 64 * HPU * 2)
#define OFF_XS   (OFF_H1D + 64 * HPU * 2)
#define SMEM_FLOATS (OFF_XS + ROWS * 4)   // 57984 floats = 231936 B

__global__ __launch_bounds__(NTHR, 1)
void lstm_persist_kernel(const float* __restrict__ x,
                         const float* __restrict__ Wih0, const float* __restrict__ Whh0,
                         const float* __restrict__ bih0, const float* __restrict__ bhh0,
                         const float* __restrict__ Wih1, const float* __restrict__ Whh1,
                         const float* __restrict__ bih1, const float* __restrict__ bhh1,
                         const float* __restrict__ Wfc,  const float* __restrict__ bfc,
                         float* __restrict__ out) {
    extern __shared__ float sm[];
    float* W0  = sm + OFF_W0;
    float* W1  = sm + OFF_W1;
    ULL* hdup0 = (ULL*)(sm + OFF_H0D);
    ULL* hdup1 = (ULL*)(sm + OFF_H1D);
    float* xs  = sm + OFF_XS;

    const int t = threadIdx.x;
    const int bid = blockIdx.x;
    const int rowbase = bid * ROWS;

    // ---- one-time staging ----
    for (int idx = t; idx < 64 * 64 * 4; idx += NTHR) {
        int gb = idx & 3, jj = (idx >> 2) & 63, k = idx >> 8;
        W0[idx] = Whh0[(gb * 64 + jj) * 64 + k];
    }
    for (int idx = t; idx < 128 * 64 * 4; idx += NTHR) {
        int gb = idx & 3, jj = (idx >> 2) & 63, k = idx >> 8;
        W1[idx] = (k < 64) ? Wih1[(gb * 64 + jj) * 64 + k]
                           : Whh1[(gb * 64 + jj) * 64 + (k - 64)];
    }
    for (int idx = t; idx < 64 * HPU; idx += NTHR) { hdup0[idx] = 0ULL; hdup1[idx] = 0ULL; }
    if (t < ROWS * 4) {
        int r = t >> 2, d = t & 3;
        xs[t] = x[((size_t)(rowbase + r) * T128 + 0) * 4 + d];  // x for step 0
    }

    // per-thread assignment: hidden unit j, row group rg (8 rows)
    const int j  = t & 63;
    const int R0 = (t >> 6) * 8;

    // gate-pair biases and input weights (i,f) / (g,o)
    const ULL bif0 = pack2(bih0[j] + bhh0[j],             bih0[64 + j] + bhh0[64 + j]);
    const ULL bgo0 = pack2(bih0[128 + j] + bhh0[128 + j], bih0[192 + j] + bhh0[192 + j]);
    const ULL bif1 = pack2(bih1[j] + bhh1[j],             bih1[64 + j] + bhh1[64 + j]);
    const ULL bgo1 = pack2(bih1[128 + j] + bhh1[128 + j], bih1[192 + j] + bhh1[192 + j]);
    ULL wif0x[4], wgo0x[4];
#pragma unroll
    for (int d = 0; d < 4; d++) {
        wif0x[d] = pack2(Wih0[j * 4 + d],         Wih0[(64 + j) * 4 + d]);
        wgo0x[d] = pack2(Wih0[(128 + j) * 4 + d], Wih0[(192 + j) * 4 + d]);
    }
    const float bfr = (t < 128) ? bfc[t & 3] : 0.0f;

    float c0[8], c1[8];
    ULL aif0[8], ago0[8], aif1[8], ago1[8];
#pragma unroll
    for (int r = 0; r < 8; r++) {
        c0[r] = 0.0f; c1[r] = 0.0f;
        aif0[r] = bif0; ago0[r] = bgo0;   // a0 for step 0 (h0 = 0; x-part added in loop)
    }
    __syncthreads();

    ULL* const h0dst = hdup0 + j * HPU + R0;
    ULL* const h1dst = hdup1 + j * HPU + R0;

    for (int s = 0; s < T128 + STEPS; s++) {
        // ---- x-part of layer-0 gates (xs holds step-s input) ----
#pragma unroll
        for (int r = 0; r < 8; r++) {
            float4 xv = *(const float4*)(xs + (R0 + r) * 4);
            ULL x0 = pack2(xv.x, xv.x), x1 = pack2(xv.y, xv.y);
            ULL x2 = pack2(xv.z, xv.z), x3 = pack2(xv.w, xv.w);
            aif0[r] = fma2(wif0x[0], x0, aif0[r]); ago0[r] = fma2(wgo0x[0], x0, ago0[r]);
            aif0[r] = fma2(wif0x[1], x1, aif0[r]); ago0[r] = fma2(wgo0x[1], x1, ago0[r]);
            aif0[r] = fma2(wif0x[2], x2, aif0[r]); ago0[r] = fma2(wgo0x[2], x2, ago0[r]);
            aif0[r] = fma2(wif0x[3], x3, aif0[r]); ago0[r] = fma2(wgo0x[3], x3, ago0[r]);
        }

        // ---- phase 1: a1 = b1 + Whh1*h1_old  INTERLEAVED with cell0 + immediate h0 store
        // (safe: old hdup0's last readers finished before B2 of previous step)
#pragma unroll
        for (int r = 0; r < 8; r++) { aif1[r] = bif1; ago1[r] = bgo1; }
#pragma unroll
        for (int kb = 0; kb < 8; kb++) {
            mv8(W1 + 64 * 64 * 4, hdup1, j, R0, kb, aif1, ago1);
            float h = cell_row(aif0[kb], ago0[kb], c0[kb]);   // MUFU hides under FMA
            h0dst[kb] = pack2(h, h);
        }
        __syncthreads();                                      // B1: new h0 visible

        // ---- phase 3: a1 += Wih1*h0_new ----
#pragma unroll
        for (int kb = 0; kb < 8; kb++) mv8(W1, hdup0, j, R0, kb, aif1, ago1);

        // prefetch next x (encode phase) — consumed at staging below
        float xpre = 0.0f;
        const bool ldx = (s + 1 < T128) && (t < ROWS * 4);
        if (ldx)
            xpre = x[((size_t)(rowbase + (t >> 2)) * T128 + (s + 1)) * 4 + (t & 3)];

        // ---- phase 5: a0_next = b0 + Whh0*h0_new  INTERLEAVED with cell1 + h1 store
        // (safe: old hdup1's last readers finished before B1 this step)
#pragma unroll
        for (int r = 0; r < 8; r++) { aif0[r] = bif0; ago0[r] = bgo0; }
#pragma unroll
        for (int kb = 0; kb < 8; kb++) {
            mv8(W0, hdup0, j, R0, kb, aif0, ago0);
            float h = cell_row(aif1[kb], ago1[kb], c1[kb]);
            h1dst[kb] = pack2(h, h);
        }
        __syncthreads();                                      // B2: new h1 visible

        // ---- head / next-step input staging ----
        if (t < ROWS * 4) {
            int r = t >> 2, d = t & 3;
            if (s >= T128) {
                const float* h1f = (const float*)hdup1;
                float p = bfr;
#pragma unroll 8
                for (int k = 0; k < 64; k++)
                    p = fmaf(__ldg(Wfc + d * 64 + k), h1f[(k * HPU + r) * 2], p);
                xs[t] = p;   // next step's input (AR)
                out[((size_t)(rowbase + r) * STEPS + (s - T128)) * 4 + d] = p;
            } else if (ldx) {
                xs[t] = xpre;  // encode phase (s==127 keeps x[127] for s==128)
            }
        }
        __syncthreads();                                      // B3: xs visible
    }
}

extern "C" void kernel_launch(void* const* d_in, const int* in_sizes, int n_in,
                              void* d_out, int out_size) {
    const float* x    = (const float*)d_in[0];
    const float* Wih0 = (const float*)d_in[1];
    const float* Whh0 = (const float*)d_in[2];
    const float* bih0 = (const float*)d_in[3];
    const float* bhh0 = (const float*)d_in[4];
    const float* Wih1 = (const float*)d_in[5];
    const float* Whh1 = (const float*)d_in[6];
    const float* bih1 = (const float*)d_in[7];
    const float* bhh1 = (const float*)d_in[8];
    const float* Wfc  = (const float*)d_in[9];
    const float* bfc  = (const float*)d_in[10];

    const int smem_bytes = SMEM_FLOATS * (int)sizeof(float);  // 231936 B
    cudaFuncSetAttribute(lstm_persist_kernel,
                         cudaFuncAttributeMaxDynamicSharedMemorySize, smem_bytes);
    lstm_persist_kernel<<<NBLK, NTHR, smem_bytes>>>(
        x, Wih0, Whh0, bih0, bhh0, Wih1, Whh1, bih1, bhh1, Wfc, bfc, (float*)d_out);
}

// round 7
// speedup vs baseline: 2.0430x; 2.0430x over previous
#include <cuda_runtime.h>

typedef unsigned long long ULL;

#define NBLK   128
#define NTHR   256
#define ROWS   32      // batch rows per block
#define T128   128
#define STEPS  60
#define HPU    34      // padded ULL stride per k-row of duplicated h (even -> 16B aligned)

__device__ __forceinline__ ULL fma2(ULL a, ULL b, ULL c) {
    ULL d;
    asm("fma.rn.f32x2 %0, %1, %2, %3;" : "=l"(d) : "l"(a), "l"(b), "l"(c));
    return d;
}
__device__ __forceinline__ ULL pack2(float x, float y) {
    ULL r;
    asm("mov.b64 %0, {%1, %2};" : "=l"(r) : "f"(x), "f"(y));
    return r;
}
__device__ __forceinline__ void unpack2(ULL v, float& x, float& y) {
    asm("mov.b64 {%0, %1}, %2;" : "=f"(x), "=f"(y) : "l"(v));
}
__device__ __forceinline__ float ex2f_(float x) {
    float y; asm("ex2.approx.f32 %0, %1;" : "=f"(y) : "f"(x)); return y;
}
__device__ __forceinline__ float rcpf_(float x) {
    float y; asm("rcp.approx.f32 %0, %1;" : "=f"(y) : "f"(x)); return y;
}
__device__ __forceinline__ float sigm(float x) {
    return rcpf_(1.0f + ex2f_(-1.4426950408889634f * x));
}
__device__ __forceinline__ float tanh_(float x) {
    return fmaf(2.0f, rcpf_(1.0f + ex2f_(-2.8853900817779268f * x)), -1.0f);
}

// 8 k-iterations of the matvec: acc_{if,go}[r] += W[k][j][{i,f},{g,o}] * hdup[k][R0+r]
// Inner unroll limited to 4 to bound ptxas's LDS batching (register pressure!).
__device__ __forceinline__ void mv8(const float* __restrict__ Wb,
                                    const ULL* __restrict__ hd,
                                    int j, int R0, int kb,
                                    ULL aif[8], ULL ago[8]) {
#pragma unroll 4
    for (int kk = 0; kk < 8; kk++) {
        int k = kb * 8 + kk;
        ulonglong2 w = *(const ulonglong2*)(Wb + ((k * 64 + j) << 2)); // w.x=(i,f) w.y=(g,o)
        const ULL* hr = hd + k * HPU + R0;
#pragma unroll
        for (int p = 0; p < 4; p++) {
            ulonglong2 hp = *(const ulonglong2*)(hr + 2 * p);  // rows 2p, 2p+1 (dup)
            aif[2 * p]     = fma2(w.x, hp.x, aif[2 * p]);
            aif[2 * p + 1] = fma2(w.x, hp.y, aif[2 * p + 1]);
            ago[2 * p]     = fma2(w.y, hp.x, ago[2 * p]);
            ago[2 * p + 1] = fma2(w.y, hp.y, ago[2 * p + 1]);
        }
    }
}

// one row of LSTM pointwise: gates (i,f) in aif, (g,o) in ago -> new c; returns new h
__device__ __forceinline__ float cell_row(ULL aif, ULL ago, float& c) {
    float gi, gf, gg, go;
    unpack2(aif, gi, gf);
    unpack2(ago, gg, go);
    float cn = sigm(gf) * c + sigm(gi) * tanh_(gg);
    c = cn;
    return sigm(go) * tanh_(cn);
}

// SMEM layout (floats):
//  W0    [64][64][4]   : Whh0 repacked, W0[(k*64+j)*4+gb] = Whh0[gb*64+j][k]
//  W1    [128][64][4]  : k<64 -> Wih1, k>=64 -> Whh1 (same repack)
//  hdup0 [64][HPU] ULL : duplicated h0 state, (h,h) per (k,row)
//  hdup1 [64][HPU] ULL
//  xs    [32][4]       : current step input per row
#define OFF_W0   0
#define OFF_W1   (OFF_W0 + 64 * 64 * 4)
#define OFF_H0D  (OFF_W1 + 128 * 64 * 4)
#define OFF_H1D  (OFF_H0D + 64 * HPU * 2)
#define OFF_XS   (OFF_H1D + 64 * HPU * 2)
#define SMEM_FLOATS (OFF_XS + ROWS * 4)   // 57984 floats = 231936 B

__global__ __launch_bounds__(NTHR, 1)
void lstm_persist_kernel(const float* __restrict__ x,
                         const float* __restrict__ Wih0, const float* __restrict__ Whh0,
                         const float* __restrict__ bih0, const float* __restrict__ bhh0,
                         const float* __restrict__ Wih1, const float* __restrict__ Whh1,
                         const float* __restrict__ bih1, const float* __restrict__ bhh1,
                         const float* __restrict__ Wfc,  const float* __restrict__ bfc,
                         float* __restrict__ out) {
    extern __shared__ float sm[];
    float* W0  = sm + OFF_W0;
    float* W1  = sm + OFF_W1;
    ULL* hdup0 = (ULL*)(sm + OFF_H0D);
    ULL* hdup1 = (ULL*)(sm + OFF_H1D);
    float* xs  = sm + OFF_XS;

    const int t = threadIdx.x;
    const int bid = blockIdx.x;
    const int rowbase = bid * ROWS;

    // ---- one-time staging ----
    for (int idx = t; idx < 64 * 64 * 4; idx += NTHR) {
        int gb = idx & 3, jj = (idx >> 2) & 63, k = idx >> 8;
        W0[idx] = Whh0[(gb * 64 + jj) * 64 + k];
    }
    for (int idx = t; idx < 128 * 64 * 4; idx += NTHR) {
        int gb = idx & 3, jj = (idx >> 2) & 63, k = idx >> 8;
        W1[idx] = (k < 64) ? Wih1[(gb * 64 + jj) * 64 + k]
                           : Whh1[(gb * 64 + jj) * 64 + (k - 64)];
    }
    for (int idx = t; idx < 64 * HPU; idx += NTHR) { hdup0[idx] = 0ULL; hdup1[idx] = 0ULL; }
    if (t < ROWS * 4) {
        int r = t >> 2, d = t & 3;
        xs[t] = x[((size_t)(rowbase + r) * T128 + 0) * 4 + d];  // x for step 0
    }

    // per-thread assignment: hidden unit j, row group rg (8 rows)
    const int j  = t & 63;
    const int R0 = (t >> 6) * 8;

    // gate-pair biases and input weights (i,f) / (g,o)
    const ULL bif0 = pack2(bih0[j] + bhh0[j],             bih0[64 + j] + bhh0[64 + j]);
    const ULL bgo0 = pack2(bih0[128 + j] + bhh0[128 + j], bih0[192 + j] + bhh0[192 + j]);
    const ULL bif1 = pack2(bih1[j] + bhh1[j],             bih1[64 + j] + bhh1[64 + j]);
    const ULL bgo1 = pack2(bih1[128 + j] + bhh1[128 + j], bih1[192 + j] + bhh1[192 + j]);
    ULL wif0x[4], wgo0x[4];
#pragma unroll
    for (int d = 0; d < 4; d++) {
        wif0x[d] = pack2(Wih0[j * 4 + d],         Wih0[(64 + j) * 4 + d]);
        wgo0x[d] = pack2(Wih0[(128 + j) * 4 + d], Wih0[(192 + j) * 4 + d]);
    }
    const float bfr = (t < 128) ? bfc[t & 3] : 0.0f;

    float c0[8], c1[8];
    ULL aif0[8], ago0[8], aif1[8], ago1[8];
#pragma unroll
    for (int r = 0; r < 8; r++) {
        c0[r] = 0.0f; c1[r] = 0.0f;
        aif0[r] = bif0; ago0[r] = bgo0;   // a0 for step 0 (h0 = 0; x-part added in loop)
    }
    __syncthreads();

    ULL* const h0dst = hdup0 + j * HPU + R0;
    ULL* const h1dst = hdup1 + j * HPU + R0;

    for (int s = 0; s < T128 + STEPS; s++) {
        // ---- x-part of layer-0 gates (xs holds step-s input) ----
#pragma unroll
        for (int r = 0; r < 8; r++) {
            float4 xv = *(const float4*)(xs + (R0 + r) * 4);
            ULL x0 = pack2(xv.x, xv.x), x1 = pack2(xv.y, xv.y);
            ULL x2 = pack2(xv.z, xv.z), x3 = pack2(xv.w, xv.w);
            aif0[r] = fma2(wif0x[0], x0, aif0[r]); ago0[r] = fma2(wgo0x[0], x0, ago0[r]);
            aif0[r] = fma2(wif0x[1], x1, aif0[r]); ago0[r] = fma2(wgo0x[1], x1, ago0[r]);
            aif0[r] = fma2(wif0x[2], x2, aif0[r]); ago0[r] = fma2(wgo0x[2], x2, ago0[r]);
            aif0[r] = fma2(wif0x[3], x3, aif0[r]); ago0[r] = fma2(wgo0x[3], x3, ago0[r]);
        }

        // ---- phase 1: a1 = b1 + Whh1*h1_old  INTERLEAVED with cell0 + immediate h0 store
        // (safe: old hdup0's last readers finished before B2 of previous step)
#pragma unroll
        for (int r = 0; r < 8; r++) { aif1[r] = bif1; ago1[r] = bgo1; }
#pragma unroll 1
        for (int kb = 0; kb < 8; kb++) {
            mv8(W1 + 64 * 64 * 4, hdup1, j, R0, kb, aif1, ago1);
            float h = cell_row(aif0[kb], ago0[kb], c0[kb]);   // MUFU hides under FMA
            h0dst[kb] = pack2(h, h);
        }
        __syncthreads();                                      // B1: new h0 visible

        // ---- phase 3: a1 += Wih1*h0_new ----
#pragma unroll 1
        for (int kb = 0; kb < 8; kb++) mv8(W1, hdup0, j, R0, kb, aif1, ago1);

        // prefetch next x (encode phase) — consumed at staging below
        float xpre = 0.0f;
        const bool ldx = (s + 1 < T128) && (t < ROWS * 4);
        if (ldx)
            xpre = x[((size_t)(rowbase + (t >> 2)) * T128 + (s + 1)) * 4 + (t & 3)];

        // ---- phase 5: a0_next = b0 + Whh0*h0_new  INTERLEAVED with cell1 + h1 store
        // (safe: old hdup1's last readers finished before B1 this step)
#pragma unroll
        for (int r = 0; r < 8; r++) { aif0[r] = bif0; ago0[r] = bgo0; }
#pragma unroll 1
        for (int kb = 0; kb < 8; kb++) {
            mv8(W0, hdup0, j, R0, kb, aif0, ago0);
            float h = cell_row(aif1[kb], ago1[kb], c1[kb]);
            h1dst[kb] = pack2(h, h);
        }
        __syncthreads();                                      // B2: new h1 visible

        // ---- head / next-step input staging ----
        if (t < ROWS * 4) {
            int r = t >> 2, d = t & 3;
            if (s >= T128) {
                const float* h1f = (const float*)hdup1;
                float p = bfr;
#pragma unroll 4
                for (int k = 0; k < 64; k++)
                    p = fmaf(__ldg(Wfc + d * 64 + k), h1f[(k * HPU + r) * 2], p);
                xs[t] = p;   // next step's input (AR)
                out[((size_t)(rowbase + r) * STEPS + (s - T128)) * 4 + d] = p;
            } else if (ldx) {
                xs[t] = xpre;  // encode phase (s==127 keeps x[127] for s==128)
            }
        }
        __syncthreads();                                      // B3: xs visible
    }
}

extern "C" void kernel_launch(void* const* d_in, const int* in_sizes, int n_in,
                              void* d_out, int out_size) {
    const float* x    = (const float*)d_in[0];
    const float* Wih0 = (const float*)d_in[1];
    const float* Whh0 = (const float*)d_in[2];
    const float* bih0 = (const float*)d_in[3];
    const float* bhh0 = (const float*)d_in[4];
    const float* Wih1 = (const float*)d_in[5];
    const float* Whh1 = (const float*)d_in[6];
    const float* bih1 = (const float*)d_in[7];
    const float* bhh1 = (const float*)d_in[8];
    const float* Wfc  = (const float*)d_in[9];
    const float* bfc  = (const float*)d_in[10];

    const int smem_bytes = SMEM_FLOATS * (int)sizeof(float);  // 231936 B
    cudaFuncSetAttribute(lstm_persist_kernel,
                         cudaFuncAttributeMaxDynamicSharedMemorySize, smem_bytes);
    lstm_persist_kernel<<<NBLK, NTHR, smem_bytes>>>(
        x, Wih0, Whh0, bih0, bhh0, Wih1, Whh1, bih1, bhh1, Wfc, bfc, (float*)d_out);
}

// round 10
// speedup vs baseline: 2.3500x; 1.1503x over previous
#include <cuda_runtime.h>

typedef unsigned long long ULL;

#define NBLK   128
#define NTHR   512
#define ROWS   32      // batch rows per block
#define RPT    4       // rows per thread
#define T128   128
#define STEPS  60
#define HPAD   36      // padded float stride per k-row of h (144B: 16B-aligned, odd 16B-groups)

__device__ __forceinline__ ULL fma2(ULL a, ULL b, ULL c) {
    ULL d;
    asm("fma.rn.f32x2 %0, %1, %2, %3;" : "=l"(d) : "l"(a), "l"(b), "l"(c));
    return d;
}
__device__ __forceinline__ ULL pack2(float x, float y) {
    ULL r;
    asm("mov.b64 %0, {%1, %2};" : "=l"(r) : "f"(x), "f"(y));
    return r;
}
__device__ __forceinline__ void unpack2(ULL v, float& x, float& y) {
    asm("mov.b64 {%0, %1}, %2;" : "=f"(x), "=f"(y) : "l"(v));
}
__device__ __forceinline__ float ex2f_(float x) {
    float y; asm("ex2.approx.f32 %0, %1;" : "=f"(y) : "f"(x)); return y;
}
__device__ __forceinline__ float rcpf_(float x) {
    float y; asm("rcp.approx.f32 %0, %1;" : "=f"(y) : "f"(x)); return y;
}
__device__ __forceinline__ float sigm(float x) {
    return rcpf_(1.0f + ex2f_(-1.4426950408889634f * x));
}
__device__ __forceinline__ float tanh_(float x) {
    return fmaf(2.0f, rcpf_(1.0f + ex2f_(-2.8853900817779268f * x)), -1.0f);
}

// 8 k-iterations: acc_{if,go}[r] += W[k][j][{i,f},{g,o}] * h[k][R0+r], r = 0..3
// h loaded plain (one broadcast LDS.128), duplicated into f32x2 lanes via ALU movs.
__device__ __forceinline__ void mv8(const float* __restrict__ Wb,
                                    const float* __restrict__ hb,
                                    int j, int R0, int kb,
                                    ULL aif[RPT], ULL ago[RPT]) {
#pragma unroll 4
    for (int kk = 0; kk < 8; kk++) {
        int k = kb * 8 + kk;
        ulonglong2 w = *(const ulonglong2*)(Wb + ((k * 64 + j) << 2)); // w.x=(i,f) w.y=(g,o)
        float4 hv = *(const float4*)(hb + k * HPAD + R0);              // rows R0..R0+3
        ULL d0 = pack2(hv.x, hv.x), d1 = pack2(hv.y, hv.y);
        ULL d2 = pack2(hv.z, hv.z), d3 = pack2(hv.w, hv.w);
        aif[0] = fma2(w.x, d0, aif[0]); ago[0] = fma2(w.y, d0, ago[0]);
        aif[1] = fma2(w.x, d1, aif[1]); ago[1] = fma2(w.y, d1, ago[1]);
        aif[2] = fma2(w.x, d2, aif[2]); ago[2] = fma2(w.y, d2, ago[2]);
        aif[3] = fma2(w.x, d3, aif[3]); ago[3] = fma2(w.y, d3, ago[3]);
    }
}

// one row of LSTM pointwise: gates (i,f) in aif, (g,o) in ago -> new c; returns new h
__device__ __forceinline__ float cell_row(ULL aif, ULL ago, float& c) {
    float gi, gf, gg, go;
    unpack2(aif, gi, gf);
    unpack2(ago, gg, go);
    float cn = sigm(gf) * c + sigm(gi) * tanh_(gg);
    c = cn;
    return sigm(go) * tanh_(cn);
}

// SMEM layout (floats):
//  W0  [64][64][4]  : Whh0 repacked, W0[(k*64+j)*4+gb] = Whh0[gb*64+j][k]
//  W1  [128][64][4] : k<64 -> Wih1, k>=64 -> Whh1 (same repack)
//  h0  [64][HPAD]   : h0 state, h0[k*HPAD + r], rows 0..31 (+4 pad)
//  h1  [64][HPAD]
//  xs  [32][4]      : current step input per row
#define OFF_W0   0
#define OFF_W1   (OFF_W0 + 64 * 64 * 4)
#define OFF_H0   (OFF_W1 + 128 * 64 * 4)
#define OFF_H1   (OFF_H0 + 64 * HPAD)
#define OFF_XS   (OFF_H1 + 64 * HPAD)
#define SMEM_FLOATS (OFF_XS + ROWS * 4)   // 53888 floats = 215552 B

__global__ __launch_bounds__(NTHR, 1)
void lstm_persist_kernel(const float* __restrict__ x,
                         const float* __restrict__ Wih0, const float* __restrict__ Whh0,
                         const float* __restrict__ bih0, const float* __restrict__ bhh0,
                         const float* __restrict__ Wih1, const float* __restrict__ Whh1,
                         const float* __restrict__ bih1, const float* __restrict__ bhh1,
                         const float* __restrict__ Wfc,  const float* __restrict__ bfc,
                         float* __restrict__ out) {
    extern __shared__ float sm[];
    float* W0  = sm + OFF_W0;
    float* W1  = sm + OFF_W1;
    float* h0s = sm + OFF_H0;
    float* h1s = sm + OFF_H1;
    float* xs  = sm + OFF_XS;

    const int t = threadIdx.x;
    const int bid = blockIdx.x;
    const int rowbase = bid * ROWS;

    // ---- one-time staging ----
    for (int idx = t; idx < 64 * 64 * 4; idx += NTHR) {
        int gb = idx & 3, jj = (idx >> 2) & 63, k = idx >> 8;
        W0[idx] = Whh0[(gb * 64 + jj) * 64 + k];
    }
    for (int idx = t; idx < 128 * 64 * 4; idx += NTHR) {
        int gb = idx & 3, jj = (idx >> 2) & 63, k = idx >> 8;
        W1[idx] = (k < 64) ? Wih1[(gb * 64 + jj) * 64 + k]
                           : Whh1[(gb * 64 + jj) * 64 + (k - 64)];
    }
    for (int idx = t; idx < 64 * HPAD; idx += NTHR) { h0s[idx] = 0.0f; h1s[idx] = 0.0f; }
    if (t < ROWS * 4) {
        int r = t >> 2, d = t & 3;
        xs[t] = x[((size_t)(rowbase + r) * T128 + 0) * 4 + d];  // x for step 0
    }

    // per-thread assignment: hidden unit j, row group rg (4 rows)
    const int j  = t & 63;
    const int R0 = (t >> 6) * RPT;

    // gate-pair biases and input weights (i,f) / (g,o)
    const ULL bif0 = pack2(bih0[j] + bhh0[j],             bih0[64 + j] + bhh0[64 + j]);
    const ULL bgo0 = pack2(bih0[128 + j] + bhh0[128 + j], bih0[192 + j] + bhh0[192 + j]);
    const ULL bif1 = pack2(bih1[j] + bhh1[j],             bih1[64 + j] + bhh1[64 + j]);
    const ULL bgo1 = pack2(bih1[128 + j] + bhh1[128 + j], bih1[192 + j] + bhh1[192 + j]);
    ULL wif0x[4], wgo0x[4];
#pragma unroll
    for (int d = 0; d < 4; d++) {
        wif0x[d] = pack2(Wih0[j * 4 + d],         Wih0[(64 + j) * 4 + d]);
        wgo0x[d] = pack2(Wih0[(128 + j) * 4 + d], Wih0[(192 + j) * 4 + d]);
    }
    const float bfr = (t < 128) ? bfc[t & 3] : 0.0f;

    float c0[RPT], c1[RPT];
    ULL aif0[RPT], ago0[RPT], aif1[RPT], ago1[RPT];
#pragma unroll
    for (int r = 0; r < RPT; r++) {
        c0[r] = 0.0f; c1[r] = 0.0f;
        aif0[r] = bif0; ago0[r] = bgo0;   // a0 for step 0 (h0 = 0; x-part added in loop)
    }
    __syncthreads();

    float* const h0dst = h0s + j * HPAD + R0;
    float* const h1dst = h1s + j * HPAD + R0;

    for (int s = 0; s < T128 + STEPS; s++) {
        // ---- x-part of layer-0 gates (xs holds step-s input) ----
#pragma unroll
        for (int r = 0; r < RPT; r++) {
            float4 xv = *(const float4*)(xs + (R0 + r) * 4);
            ULL x0 = pack2(xv.x, xv.x), x1 = pack2(xv.y, xv.y);
            ULL x2 = pack2(xv.z, xv.z), x3 = pack2(xv.w, xv.w);
            aif0[r] = fma2(wif0x[0], x0, aif0[r]); ago0[r] = fma2(wgo0x[0], x0, ago0[r]);
            aif0[r] = fma2(wif0x[1], x1, aif0[r]); ago0[r] = fma2(wgo0x[1], x1, ago0[r]);
            aif0[r] = fma2(wif0x[2], x2, aif0[r]); ago0[r] = fma2(wgo0x[2], x2, ago0[r]);
            aif0[r] = fma2(wif0x[3], x3, aif0[r]); ago0[r] = fma2(wgo0x[3], x3, ago0[r]);
        }

        // ---- phase 1: a1 = b1 + Whh1*h1_old  INTERLEAVED with cell0 (MUFU under FMA)
        float h0n[RPT];
#pragma unroll
        for (int r = 0; r < RPT; r++) { aif1[r] = bif1; ago1[r] = bgo1; }
#pragma unroll 1
        for (int kb = 0; kb < 8; kb++) {
            mv8(W1 + 64 * 64 * 4, h1s, j, R0, kb, aif1, ago1);
            if (kb & 1) {
                int r = kb >> 1;
                h0n[r] = cell_row(aif0[r], ago0[r], c0[r]);
            }
        }
        *(float4*)h0dst = make_float4(h0n[0], h0n[1], h0n[2], h0n[3]);
        __syncthreads();                                      // B1: new h0 visible

        // ---- phase 3: a1 += Wih1*h0_new ----
#pragma unroll 1
        for (int kb = 0; kb < 8; kb++) mv8(W1, h0s, j, R0, kb, aif1, ago1);

        // prefetch next x (encode phase) — consumed at staging below
        float xpre = 0.0f;
        const bool ldx = (s + 1 < T128) && (t < ROWS * 4);
        if (ldx)
            xpre = x[((size_t)(rowbase + (t >> 2)) * T128 + (s + 1)) * 4 + (t & 3)];

        // ---- phase 5: a0_next = b0 + Whh0*h0_new  INTERLEAVED with cell1
        float h1n[RPT];
#pragma unroll
        for (int r = 0; r < RPT; r++) { aif0[r] = bif0; ago0[r] = bgo0; }
#pragma unroll 1
        for (int kb = 0; kb < 8; kb++) {
            mv8(W0, h0s, j, R0, kb, aif0, ago0);
            if (kb & 1) {
                int r = kb >> 1;
                h1n[r] = cell_row(aif1[r], ago1[r], c1[r]);
            }
        }
        *(float4*)h1dst = make_float4(h1n[0], h1n[1], h1n[2], h1n[3]);
        __syncthreads();                                      // B2: new h1 visible

        // ---- head / next-step input staging ----
        if (t < ROWS * 4) {
            int r = t >> 2, d = t & 3;
            if (s >= T128) {
                float p = bfr;
#pragma unroll 4
                for (int k = 0; k < 64; k++)
                    p = fmaf(__ldg(Wfc + d * 64 + k), h1s[k * HPAD + r], p);
                xs[t] = p;   // next step's input (AR)
                out[((size_t)(rowbase + r) * STEPS + (s - T128)) * 4 + d] = p;
            } else if (ldx) {
                xs[t] = xpre;  // encode phase (s==127 keeps x[127] for s==128)
            }
        }
        __syncthreads();                                      // B3: xs visible
    }
}

extern "C" void kernel_launch(void* const* d_in, const int* in_sizes, int n_in,
                              void* d_out, int out_size) {
    const float* x    = (const float*)d_in[0];
    const float* Wih0 = (const float*)d_in[1];
    const float* Whh0 = (const float*)d_in[2];
    const float* bih0 = (const float*)d_in[3];
    const float* bhh0 = (const float*)d_in[4];
    const float* Wih1 = (const float*)d_in[5];
    const float* Whh1 = (const float*)d_in[6];
    const float* bih1 = (const float*)d_in[7];
    const float* bhh1 = (const float*)d_in[8];
    const float* Wfc  = (const float*)d_in[9];
    const float* bfc  = (const float*)d_in[10];

    const int smem_bytes = SMEM_FLOATS * (int)sizeof(float);  // 215552 B
    cudaFuncSetAttribute(lstm_persist_kernel,
                         cudaFuncAttributeMaxDynamicSharedMemorySize, smem_bytes);
    lstm_persist_kernel<<<NBLK, NTHR, smem_bytes>>>(
        x, Wih0, Whh0, bih0, bhh0, Wih1, Whh1, bih1, bhh1, Wfc, bfc, (float*)d_out);
}

// round 14
// speedup vs baseline: 2.6390x; 1.1230x over previous
#include <cuda_runtime.h>

typedef unsigned long long ULL;

#define NBLK   128
#define NTHR   512
#define ROWS   32      // batch rows per block
#define T128   128
#define STEPS  60
#define HPAD   36      // padded float stride per k-row of h

__device__ __forceinline__ ULL fma2(ULL a, ULL b, ULL c) {
    ULL d;
    asm("fma.rn.f32x2 %0, %1, %2, %3;" : "=l"(d) : "l"(a), "l"(b), "l"(c));
    return d;
}
__device__ __forceinline__ ULL pack2(float x, float y) {
    ULL r;
    asm("mov.b64 %0, {%1, %2};" : "=l"(r) : "f"(x), "f"(y));
    return r;
}
__device__ __forceinline__ void unpack2(ULL v, float& x, float& y) {
    asm("mov.b64 {%0, %1}, %2;" : "=f"(x), "=f"(y) : "l"(v));
}
__device__ __forceinline__ float ex2f_(float x) {
    float y; asm("ex2.approx.f32 %0, %1;" : "=f"(y) : "f"(x)); return y;
}
__device__ __forceinline__ float rcpf_(float x) {
    float y; asm("rcp.approx.f32 %0, %1;" : "=f"(y) : "f"(x)); return y;
}
__device__ __forceinline__ float sigm(float x) {
    return rcpf_(1.0f + ex2f_(-1.4426950408889634f * x));
}
__device__ __forceinline__ float tanh_(float x) {
    return fmaf(2.0f, rcpf_(1.0f + ex2f_(-2.8853900817779268f * x)), -1.0f);
}

// 8 k-iters, single matvec: acc_{if,go}[r] += W[k][j][{i,f},{g,o}] * h[k][R0+r]
__device__ __forceinline__ void mv8(const float* __restrict__ Wb,
                                    const float* __restrict__ hb,
                                    int j, int R0, int kb,
                                    ULL aif[4], ULL ago[4]) {
#pragma unroll 4
    for (int kk = 0; kk < 8; kk++) {
        int k = kb * 8 + kk;
        ulonglong2 w = *(const ulonglong2*)(Wb + ((k * 64 + j) << 2)); // (i,f),(g,o)
        float4 hv = *(const float4*)(hb + k * HPAD + R0);
        ULL d0 = pack2(hv.x, hv.x), d1 = pack2(hv.y, hv.y);
        ULL d2 = pack2(hv.z, hv.z), d3 = pack2(hv.w, hv.w);
        aif[0] = fma2(w.x, d0, aif[0]); ago[0] = fma2(w.y, d0, ago[0]);
        aif[1] = fma2(w.x, d1, aif[1]); ago[1] = fma2(w.y, d1, ago[1]);
        aif[2] = fma2(w.x, d2, aif[2]); ago[2] = fma2(w.y, d2, ago[2]);
        aif[3] = fma2(w.x, d3, aif[3]); ago[3] = fma2(w.y, d3, ago[3]);
    }
}

// 8 k-iters, fused: one h load feeds BOTH (Wih1 -> a1) and (Whh0 -> a0next)
__device__ __forceinline__ void mv8_fused(const float* __restrict__ W1b,
                                          const float* __restrict__ W0b,
                                          const float* __restrict__ hb,
                                          int j, int R0, int kb,
                                          ULL aif1[4], ULL ago1[4],
                                          ULL aif0[4], ULL ago0[4]) {
#pragma unroll 2
    for (int kk = 0; kk < 8; kk++) {
        int k = kb * 8 + kk;
        ulonglong2 w1 = *(const ulonglong2*)(W1b + ((k * 64 + j) << 2));
        ulonglong2 w0 = *(const ulonglong2*)(W0b + ((k * 64 + j) << 2));
        float4 hv = *(const float4*)(hb + k * HPAD + R0);
        ULL d0 = pack2(hv.x, hv.x), d1 = pack2(hv.y, hv.y);
        ULL d2 = pack2(hv.z, hv.z), d3 = pack2(hv.w, hv.w);
        aif1[0] = fma2(w1.x, d0, aif1[0]); ago1[0] = fma2(w1.y, d0, ago1[0]);
        aif0[0] = fma2(w0.x, d0, aif0[0]); ago0[0] = fma2(w0.y, d0, ago0[0]);
        aif1[1] = fma2(w1.x, d1, aif1[1]); ago1[1] = fma2(w1.y, d1, ago1[1]);
        aif0[1] = fma2(w0.x, d1, aif0[1]); ago0[1] = fma2(w0.y, d1, ago0[1]);
        aif1[2] = fma2(w1.x, d2, aif1[2]); ago1[2] = fma2(w1.y, d2, ago1[2]);
        aif0[2] = fma2(w0.x, d2, aif0[2]); ago0[2] = fma2(w0.y, d2, ago0[2]);
        aif1[3] = fma2(w1.x, d3, aif1[3]); ago1[3] = fma2(w1.y, d3, ago1[3]);
        aif0[3] = fma2(w0.x, d3, aif0[3]); ago0[3] = fma2(w0.y, d3, ago0[3]);
    }
}

// one row of LSTM pointwise -> new c (in-place), returns new h
__device__ __forceinline__ float cell_row(ULL aif, ULL ago, float& c) {
    float gi, gf, gg, go;
    unpack2(aif, gi, gf);
    unpack2(ago, gg, go);
    float cn = sigm(gf) * c + sigm(gi) * tanh_(gg);
    c = cn;
    return sigm(go) * tanh_(cn);
}

// SMEM layout (floats): W repack W[(k*64+j)*4+g] = Wsrc[(g*64+j)*64+k]
#define OFF_W0    0                      // Whh0  [64][64][4]
#define OFF_W1IH  (OFF_W0 + 16384)       // Wih1
#define OFF_W1HH  (OFF_W1IH + 16384)     // Whh1
#define OFF_H0    (OFF_W1HH + 16384)     // h0 [64][HPAD]
#define OFF_H1    (OFF_H0 + 64 * HPAD)
#define OFF_XS    (OFF_H1 + 64 * HPAD)   // xs[32][4]
#define SMEM_FLOATS (OFF_XS + ROWS * 4)  // 53888 floats = 215552 B

__global__ __launch_bounds__(NTHR, 1)
void lstm_persist_kernel(const float* __restrict__ x,
                         const float* __restrict__ Wih0, const float* __restrict__ Whh0,
                         const float* __restrict__ bih0, const float* __restrict__ bhh0,
                         const float* __restrict__ Wih1, const float* __restrict__ Whh1,
                         const float* __restrict__ bih1, const float* __restrict__ bhh1,
                         const float* __restrict__ Wfc,  const float* __restrict__ bfc,
                         float* __restrict__ out) {
    extern __shared__ float sm[];
    float* W0h  = sm + OFF_W0;
    float* W1i  = sm + OFF_W1IH;
    float* W1h  = sm + OFF_W1HH;
    float* h0s  = sm + OFF_H0;
    float* h1s  = sm + OFF_H1;
    float* xs   = sm + OFF_XS;

    const int t = threadIdx.x;
    const int rowbase = blockIdx.x * ROWS;

    // ---- one-time staging ----
    for (int idx = t; idx < 16384; idx += NTHR) {
        int g = idx & 3, jj = (idx >> 2) & 63, k = idx >> 8;
        W0h[idx] = Whh0[(g * 64 + jj) * 64 + k];
        W1i[idx] = Wih1[(g * 64 + jj) * 64 + k];
        W1h[idx] = Whh1[(g * 64 + jj) * 64 + k];
    }
    for (int idx = t; idx < 64 * HPAD; idx += NTHR) { h0s[idx] = 0.0f; h1s[idx] = 0.0f; }
    if (t < ROWS * 4)
        xs[t] = x[((size_t)(rowbase + (t >> 2)) * T128) * 4 + (t & 3)];

    // ---- warp tiling: 16 j x 2 row-groups per warp (W reads 2wf/k, h 1wf/k) ----
    const int wid = t >> 5, l = t & 31;
    const int j  = (wid & 3) * 16 + (l & 15);
    const int R0 = (wid >> 2) * 8 + (l >> 4) * 4;

    const ULL bif0 = pack2(bih0[j] + bhh0[j],             bih0[64 + j] + bhh0[64 + j]);
    const ULL bgo0 = pack2(bih0[128 + j] + bhh0[128 + j], bih0[192 + j] + bhh0[192 + j]);
    const ULL bif1 = pack2(bih1[j] + bhh1[j],             bih1[64 + j] + bhh1[64 + j]);
    const ULL bgo1 = pack2(bih1[128 + j] + bhh1[128 + j], bih1[192 + j] + bhh1[192 + j]);
    ULL wif0x[4], wgo0x[4];
#pragma unroll
    for (int d = 0; d < 4; d++) {
        wif0x[d] = pack2(Wih0[j * 4 + d],         Wih0[(64 + j) * 4 + d]);
        wgo0x[d] = pack2(Wih0[(128 + j) * 4 + d], Wih0[(192 + j) * 4 + d]);
    }
    const float bfr = (t < 128) ? bfc[t & 3] : 0.0f;

    float c0[4], c1[4];
    ULL aif0[4], ago0[4], aif1[4], ago1[4];
#pragma unroll
    for (int r = 0; r < 4; r++) {
        c0[r] = 0.0f; c1[r] = 0.0f;
        aif0[r] = bif0; ago0[r] = bgo0;   // carried a0 for step 0 (h0_prev = 0)
    }
    __syncthreads();

    float* const h0dst = h0s + j * HPAD + R0;
    float* const h1dst = h1s + j * HPAD + R0;

    for (int s = 0; s < T128 + STEPS; s++) {
        // ---- x-part of layer-0 gates (a0 carries b0 + Whh0*h0_prev from fused loop) ----
#pragma unroll
        for (int r = 0; r < 4; r++) {
            float4 xv = *(const float4*)(xs + (R0 + r) * 4);
            ULL x0 = pack2(xv.x, xv.x), x1 = pack2(xv.y, xv.y);
            ULL x2 = pack2(xv.z, xv.z), x3 = pack2(xv.w, xv.w);
            aif0[r] = fma2(wif0x[0], x0, aif0[r]); ago0[r] = fma2(wgo0x[0], x0, ago0[r]);
            aif0[r] = fma2(wif0x[1], x1, aif0[r]); ago0[r] = fma2(wgo0x[1], x1, ago0[r]);
            aif0[r] = fma2(wif0x[2], x2, aif0[r]); ago0[r] = fma2(wgo0x[2], x2, ago0[r]);
            aif0[r] = fma2(wif0x[3], x3, aif0[r]); ago0[r] = fma2(wgo0x[3], x3, ago0[r]);
        }

        // ---- phase 1: a1 = b1 + Whh1*h1_old, interleaved cell0 (MUFU under FMA) ----
        float h0n[4];
#pragma unroll
        for (int r = 0; r < 4; r++) { aif1[r] = bif1; ago1[r] = bgo1; }
#pragma unroll 1
        for (int kb = 0; kb < 8; kb++) {
            mv8(W1h, h1s, j, R0, kb, aif1, ago1);
            if (kb & 1) {
                int r = kb >> 1;
                h0n[r] = cell_row(aif0[r], ago0[r], c0[r]);
            }
        }
        *(float4*)h0dst = make_float4(h0n[0], h0n[1], h0n[2], h0n[3]);
        __syncthreads();                                      // B1: new h0 visible

        // prefetch next x (encode phase) — latency hides under fused loop
        float xpre = 0.0f;
        const bool ldx = (s + 1 < T128) && (t < ROWS * 4);
        if (ldx)
            xpre = x[((size_t)(rowbase + (t >> 2)) * T128 + (s + 1)) * 4 + (t & 3)];

        // ---- fused phase: a1 += Wih1*h0_new ; a0_next = b0 + Whh0*h0_new ----
#pragma unroll
        for (int r = 0; r < 4; r++) { aif0[r] = bif0; ago0[r] = bgo0; }
#pragma unroll 1
        for (int kb = 0; kb < 8; kb++)
            mv8_fused(W1i, W0h, h0s, j, R0, kb, aif1, ago1, aif0, ago0);

        // ---- cell1 burst -> h1 store ----
        float h1n[4];
#pragma unroll
        for (int r = 0; r < 4; r++) h1n[r] = cell_row(aif1[r], ago1[r], c1[r]);
        *(float4*)h1dst = make_float4(h1n[0], h1n[1], h1n[2], h1n[3]);
        __syncthreads();                                      // B2: new h1 visible

        // ---- head (AR) / next-step input staging ----
        if (t < ROWS * 4) {
            int r = t >> 2, d = t & 3;
            if (s >= T128) {
                float p = bfr;
#pragma unroll 4
                for (int k = 0; k < 64; k++)
                    p = fmaf(__ldg(Wfc + d * 64 + k), h1s[k * HPAD + r], p);
                xs[t] = p;
                out[((size_t)(rowbase + r) * STEPS + (s - T128)) * 4 + d] = p;
            } else if (ldx) {
                xs[t] = xpre;  // encode phase (s==127 keeps x[127] for s==128)
            }
        }
        __syncthreads();                                      // B3: xs visible
    }
}

extern "C" void kernel_launch(void* const* d_in, const int* in_sizes, int n_in,
                              void* d_out, int out_size) {
    const float* x    = (const float*)d_in[0];
    const float* Wih0 = (const float*)d_in[1];
    const float* Whh0 = (const float*)d_in[2];
    const float* bih0 = (const float*)d_in[3];
    const float* bhh0 = (const float*)d_in[4];
    const float* Wih1 = (const float*)d_in[5];
    const float* Whh1 = (const float*)d_in[6];
    const float* bih1 = (const float*)d_in[7];
    const float* bhh1 = (const float*)d_in[8];
    const float* Wfc  = (const float*)d_in[9];
    const float* bfc  = (const float*)d_in[10];

    const int smem_bytes = SMEM_FLOATS * (int)sizeof(float);  // 215552 B
    cudaFuncSetAttribute(lstm_persist_kernel,
                         cudaFuncAttributeMaxDynamicSharedMemorySize, smem_bytes);
    lstm_persist_kernel<<<NBLK, NTHR, smem_bytes>>>(
        x, Wih0, Whh0, bih0, bhh0, Wih1, Whh1, bih1, bhh1, Wfc, bfc, (float*)d_out);
}